// round 16
// baseline (speedup 1.0000x reference)
#include <cuda_runtime.h>
#include <cstdint>

// resRNN: x(256,1024,8), W1(521,512), b1(512), W2(512,1), b2(1)
// out = [output(256,1024,1) | implied_storage(256,1024,1)]
//
// R6 body exactly; ONLY the per-step sync changed: cluster-wide barrier ->
// per-CTA smem mbarrier (count 8), tid0 arrives on all 8 CTAs' bars
// (release.cluster), all threads try_wait (acquire.cluster) on local bar.

#define TPB 256

static __device__ float g_hx[2][256][512];       // double-buffered hidden state
static __device__ float g_part[2][16][8][16];    // per-(rg,cg,row) readout partials

// shared memory layout (float offsets); inpT stride = 20
#define OFF_W    0              // 544*64   = 34816 floats
#define OFF_IT   34816          // 544*20   = 10880 floats (inpT[k][20])
#define OFF_RED  45696          // 8*16*68  =  8704 floats
#define OFF_B1   54400          // 64
#define OFF_W2   54464          // 64
#define OFF_S    54528          // 16
#define OFF_BAR_BYTES (54544 * 4)   // 8-byte mbarrier, 8B-aligned
#define SMEM_BYTES (OFF_BAR_BYTES + 8)

__device__ __forceinline__ uint32_t smem_u32(const void* p) {
    uint32_t a;
    asm("{ .reg .u64 t; cvta.to.shared.u64 t, %1; cvt.u32.u64 %0, t; }" : "=r"(a) : "l"(p));
    return a;
}
__device__ __forceinline__ uint32_t mapa_sh(uint32_t addr, uint32_t rank) {
    uint32_t r;
    asm("mapa.shared::cluster.u32 %0, %1, %2;" : "=r"(r) : "r"(addr), "r"(rank));
    return r;
}
__device__ __forceinline__ void bar_arrive_remote(uint32_t remaddr) {
    asm volatile("mbarrier.arrive.release.cluster.shared::cluster.b64 _, [%0];"
                 :: "r"(remaddr) : "memory");
}
__device__ __forceinline__ void bar_wait_parity(uint32_t addr, uint32_t parity) {
    uint32_t done;
    asm volatile(
        "{\n\t.reg .pred p;\n\t"
        "mbarrier.try_wait.parity.acquire.cluster.shared::cta.b64 p, [%1], %2, 0x989680;\n\t"
        "selp.b32 %0, 1, 0, p;\n\t}"
        : "=r"(done) : "r"(addr), "r"(parity) : "memory");
    while (!done) {
        asm volatile(
            "{\n\t.reg .pred p;\n\t"
            "mbarrier.try_wait.parity.acquire.cluster.shared::cta.b64 p, [%1], %2, 0x989680;\n\t"
            "selp.b32 %0, 1, 0, p;\n\t}"
            : "=r"(done) : "r"(addr), "r"(parity) : "memory");
    }
}

__global__ void __cluster_dims__(8, 1, 1) __launch_bounds__(256, 1)
resRNN_kernel(const float* __restrict__ x, const float* __restrict__ W1,
              const float* __restrict__ b1, const float* __restrict__ W2,
              const float* __restrict__ b2, float* __restrict__ dout)
{
    extern __shared__ float sm[];
    float* Wsm  = sm + OFF_W;
    float* inpT = sm + OFF_IT;
    float* red  = sm + OFF_RED;
    float* b1s  = sm + OFF_B1;
    float* w2s  = sm + OFF_W2;
    float* s_sm = sm + OFF_S;
    const uint32_t barAddr = smem_u32((char*)sm + OFF_BAR_BYTES);

    const int tid  = threadIdx.x;
    const int warp = tid >> 5;     // k-partition 0..7
    const int lane = tid & 31;
    const int cg   = blockIdx.x;   // colgroup 0..7
    const int rg   = blockIdx.y;   // rowgroup 0..15
    const int row0 = rg * 16;

    // ---- init: load W1 slice [544 x 64] (zero-pad k>=521), zero inpT ----
    for (int i = tid; i < 544 * 16; i += TPB) {
        int k = i >> 4, f4 = i & 15;
        float4 v = make_float4(0.f, 0.f, 0.f, 0.f);
        if (k < 521) v = *(const float4*)&W1[k * 512 + cg * 64 + f4 * 4];
        *(float4*)&Wsm[k * 64 + f4 * 4] = v;
    }
    for (int i = tid; i < 544 * 20; i += TPB) inpT[i] = 0.f;
    if (tid < 64) { b1s[tid] = b1[cg * 64 + tid]; w2s[tid] = W2[cg * 64 + tid]; }
    if (tid == 0)
        asm volatile("mbarrier.init.shared.b64 [%0], 8;" :: "r"(barAddr) : "memory");
    const float b2v = b2[0];
    float* outp = dout;
    float* stop = dout + 256 * 1024;

    // per-rank remote bar addresses (used by tid 0 only)
    uint32_t remBar[8];
    #pragma unroll
    for (int p = 0; p < 8; ++p) remBar[p] = mapa_sh(barAddr, (uint32_t)p);

    // pre-loop: stage x_0 into inpT, s_0 = x_0[0]; prefetch x_1
    const int xr = tid >> 3, xc = tid & 7;
    float xpre = 0.f, x0pre = 0.f;
    if (tid < 128) {
        float xv = x[(row0 + xr) * 8192 + xc];
        inpT[xc * 20 + xr] = xv;
        xpre = x[(row0 + xr) * 8192 + 8 + xc];         // x_1
    }
    if (tid < 16) {
        float s = x[(row0 + tid) * 8192];              // s_0 = x_0[0] (prev out = 0)
        s_sm[tid] = s;
        inpT[8 * 20 + tid] = s;
        if (cg == 0) stop[(row0 + tid) * 1024] = s;
        x0pre = x[(row0 + tid) * 8192 + 8];            // x_1[0]
    }
    __syncthreads();
    // one-time: all mbarrier inits visible cluster-wide before any arrive
    asm volatile("barrier.cluster.arrive.aligned;" ::: "memory");
    asm volatile("barrier.cluster.wait.aligned;" ::: "memory");

    for (int t = 0; t < 1024; ++t) {
        const int pw = t & 1;        // write parity
        const int pr = pw ^ 1;       // read parity = (t-1)&1

        // ---- Phase A: gather out_{t-1}; mass balance; transpose hx into inpT ----
        if (t > 0) {
            if (tid < 16) {
                float o = b2v;
                #pragma unroll
                for (int g = 0; g < 8; ++g) o += __ldcg(&g_part[pr][rg][g][tid]);
                float s = s_sm[tid] + x0pre - o;      // s_t = s_{t-1} + x_t[0] - o
                s_sm[tid] = s;
                inpT[8 * 20 + tid] = s;
                if (cg == 0) {
                    outp[(row0 + tid) * 1024 + (t - 1)] = o;
                    stop[(row0 + tid) * 1024 + t] = s;
                }
            }
            // hx transpose: thread owns hidden cols tid and tid+256
            float v0[16], v1[16];
            #pragma unroll
            for (int r = 0; r < 16; ++r) v0[r] = __ldcg(&g_hx[pr][row0 + r][tid]);
            #pragma unroll
            for (int r = 0; r < 16; ++r) v1[r] = __ldcg(&g_hx[pr][row0 + r][tid + 256]);
            float* d0 = &inpT[(9 + tid) * 20];
            float* d1 = &inpT[(9 + tid + 256) * 20];
            #pragma unroll
            for (int q = 0; q < 8; ++q) {
                *(float2*)(d0 + 2 * q) = make_float2(v0[2*q], v0[2*q+1]);
                *(float2*)(d1 + 2 * q) = make_float2(v1[2*q], v1[2*q+1]);
            }
        }
        __syncthreads();

        // ---- Phase C: mainloop (R6-identical) ----
        unsigned long long acc0[8], acc1[8];
        #pragma unroll
        for (int i = 0; i < 8; ++i) { acc0[i] = 0ull; acc1[i] = 0ull; }
        {
            const float* Ip = inpT + warp * 68 * 20;
            const float* Wp = Wsm + warp * 68 * 64 + 2 * lane;
            #pragma unroll 4
            for (int kk = 0; kk < 68; ++kk) {
                unsigned long long pr_[8];
                #pragma unroll
                for (int j = 0; j < 4; ++j) {
                    ulonglong2 q = *(const ulonglong2*)(Ip + kk * 20 + 4 * j);
                    pr_[2 * j] = q.x; pr_[2 * j + 1] = q.y;
                }
                float2 wv = *(const float2*)(Wp + kk * 64);
                unsigned long long w00, w11;
                asm("mov.b64 %0, {%1, %1};" : "=l"(w00) : "f"(wv.x));
                asm("mov.b64 %0, {%1, %1};" : "=l"(w11) : "f"(wv.y));
                #pragma unroll
                for (int p = 0; p < 8; ++p) {
                    asm("fma.rn.f32x2 %0, %1, %2, %0;" : "+l"(acc0[p]) : "l"(pr_[p]), "l"(w00));
                    asm("fma.rn.f32x2 %0, %1, %2, %0;" : "+l"(acc1[p]) : "l"(pr_[p]), "l"(w11));
                }
            }
        }

        // ---- Phase D: spill, reduce, tanh, publish (R6-identical) ----
        #pragma unroll
        for (int p = 0; p < 8; ++p) {
            float2 a0 = *(float2*)&acc0[p];
            float2 a1 = *(float2*)&acc1[p];
            *(float2*)&red[(warp * 16 + 2 * p)     * 68 + 2 * lane] = make_float2(a0.x, a1.x);
            *(float2*)&red[(warp * 16 + 2 * p + 1) * 68 + 2 * lane] = make_float2(a0.y, a1.y);
        }
        __syncthreads();
        {
            int r = tid >> 4, c4 = (tid & 15) * 4;
            float4 v = make_float4(0.f, 0.f, 0.f, 0.f);
            #pragma unroll
            for (int w = 0; w < 8; ++w) {
                float4 p = *(const float4*)&red[(w * 16 + r) * 68 + c4];
                v.x += p.x; v.y += p.y; v.z += p.z; v.w += p.w;
            }
            v.x = tanhf(v.x + b1s[c4 + 0]);
            v.y = tanhf(v.y + b1s[c4 + 1]);
            v.z = tanhf(v.z + b1s[c4 + 2]);
            v.w = tanhf(v.w + b1s[c4 + 3]);
            *(float4*)&g_hx[pw][row0 + r][cg * 64 + c4] = v;
            float p = v.x * w2s[c4] + v.y * w2s[c4 + 1] + v.z * w2s[c4 + 2] + v.w * w2s[c4 + 3];
            #pragma unroll
            for (int off = 8; off > 0; off >>= 1)
                p += __shfl_xor_sync(0xffffffffu, p, off);
            if ((tid & 15) == 0) g_part[pw][rg][cg][r] = p;
        }
        __syncthreads();     // all publishes done CTA-wide before the arrive

        // ---- Phase E: mbarrier sync; x staging in the gap ----
        if (tid == 0) {
            #pragma unroll
            for (int p = 0; p < 8; ++p) bar_arrive_remote(remBar[p]);
        }
        if (t < 1023) {
            if (tid < 128) {
                inpT[xc * 20 + xr] = xpre;                           // stage x_{t+1}
                if (t < 1022) xpre = x[(row0 + xr) * 8192 + (t + 2) * 8 + xc];
            }
            if (tid < 16) x0pre = x[(row0 + tid) * 8192 + (t + 1) * 8];
        }
        bar_wait_parity(barAddr, (uint32_t)(t & 1));
    }

    // epilogue: final output value out_{L-1} (ordered by last acquire-wait)
    if (cg == 0 && tid < 16) {
        float o = b2v;
        #pragma unroll
        for (int g = 0; g < 8; ++g) o += __ldcg(&g_part[1][rg][g][tid]);
        outp[(row0 + tid) * 1024 + 1023] = o;
    }
}

extern "C" void kernel_launch(void* const* d_in, const int* in_sizes, int n_in,
                              void* d_out, int out_size) {
    const float* x  = (const float*)d_in[0];
    const float* W1 = (const float*)d_in[1];
    const float* b1 = (const float*)d_in[2];
    const float* W2 = (const float*)d_in[3];
    const float* b2 = (const float*)d_in[4];
    float* out = (float*)d_out;

    cudaFuncSetAttribute(resRNN_kernel, cudaFuncAttributeMaxDynamicSharedMemorySize, SMEM_BYTES);

    dim3 grid(8, 16, 1);   // cluster_dims (8,1,1): one cluster per rowgroup
    dim3 block(TPB, 1, 1);
    resRNN_kernel<<<grid, block, SMEM_BYTES>>>(x, W1, b1, W2, b2, out);
}

// round 17
// speedup vs baseline: 1.4527x; 1.4527x over previous
#include <cuda_runtime.h>
#include <cstdint>

// resRNN: x(256,1024,8), W1(521,512), b1(512), W2(512,1), b2(1)
// out = [output(256,1024,1) | implied_storage(256,1024,1)]
//
// R6 kernel (proven replay-stable) with ONE change: software-pipelined
// mainloop (rotating register prefetch: iter kk+1's LDS issue during iter
// kk's FMAs -> LDS latency structurally hidden at 2 warps/SMSP).

#define TPB 256

static __device__ float g_hx[2][256][512];       // double-buffered hidden state
static __device__ float g_part[2][16][8][16];    // per-(rg,cg,row) readout partials

// shared memory layout (float offsets); inpT stride = 20 (16 rows + 4 pad)
#define OFF_W    0              // 544*64   = 34816 floats
#define OFF_IT   34816          // 544*20   = 10880 floats (inpT[k][20])
#define OFF_RED  45696          // 8*16*68  =  8704 floats
#define OFF_B1   54400          // 64
#define OFF_W2   54464          // 64
#define OFF_S    54528          // 16
#define SMEM_FLOATS 54544
#define SMEM_BYTES (SMEM_FLOATS * 4)

__global__ void __cluster_dims__(8, 1, 1) __launch_bounds__(256, 1)
resRNN_kernel(const float* __restrict__ x, const float* __restrict__ W1,
              const float* __restrict__ b1, const float* __restrict__ W2,
              const float* __restrict__ b2, float* __restrict__ dout)
{
    extern __shared__ float sm[];
    float* Wsm  = sm + OFF_W;
    float* inpT = sm + OFF_IT;
    float* red  = sm + OFF_RED;
    float* b1s  = sm + OFF_B1;
    float* w2s  = sm + OFF_W2;
    float* s_sm = sm + OFF_S;

    const int tid  = threadIdx.x;
    const int warp = tid >> 5;     // k-partition 0..7
    const int lane = tid & 31;
    const int cg   = blockIdx.x;   // colgroup 0..7
    const int rg   = blockIdx.y;   // rowgroup 0..15
    const int row0 = rg * 16;

    // ---- init: load W1 slice [544 x 64] (zero-pad k>=521), zero inpT ----
    for (int i = tid; i < 544 * 16; i += TPB) {
        int k = i >> 4, f4 = i & 15;
        float4 v = make_float4(0.f, 0.f, 0.f, 0.f);
        if (k < 521) v = *(const float4*)&W1[k * 512 + cg * 64 + f4 * 4];
        *(float4*)&Wsm[k * 64 + f4 * 4] = v;
    }
    for (int i = tid; i < 544 * 20; i += TPB) inpT[i] = 0.f;
    if (tid < 64) { b1s[tid] = b1[cg * 64 + tid]; w2s[tid] = W2[cg * 64 + tid]; }
    const float b2v = b2[0];
    float* outp = dout;
    float* stop = dout + 256 * 1024;

    // pre-loop: stage x_0 into inpT, s_0 = x_0[0]; prefetch x_1
    const int xr = tid >> 3, xc = tid & 7;
    float xpre = 0.f, x0pre = 0.f;
    if (tid < 128) {
        float xv = x[(row0 + xr) * 8192 + xc];
        inpT[xc * 20 + xr] = xv;
        xpre = x[(row0 + xr) * 8192 + 8 + xc];         // x_1
    }
    if (tid < 16) {
        float s = x[(row0 + tid) * 8192];              // s_0 = x_0[0] (prev out = 0)
        s_sm[tid] = s;
        inpT[8 * 20 + tid] = s;
        if (cg == 0) stop[(row0 + tid) * 1024] = s;
        x0pre = x[(row0 + tid) * 8192 + 8];            // x_1[0] (for Phase A at t=1)
    }
    __syncthreads();

    for (int t = 0; t < 1024; ++t) {
        const int pw = t & 1;        // write parity
        const int pr = pw ^ 1;       // read parity = (t-1)&1

        // ---- Phase A: gather out_{t-1}; mass balance; transpose hx into inpT ----
        if (t > 0) {
            if (tid < 16) {
                float o = b2v;
                #pragma unroll
                for (int g = 0; g < 8; ++g) o += __ldcg(&g_part[pr][rg][g][tid]);
                // s_t = s_{t-1} + x_t[0] - out_{t-1}
                float s = s_sm[tid] + x0pre - o;
                s_sm[tid] = s;
                inpT[8 * 20 + tid] = s;
                if (cg == 0) {
                    outp[(row0 + tid) * 1024 + (t - 1)] = o;
                    stop[(row0 + tid) * 1024 + t] = s;
                }
            }
            // hx transpose: thread owns hidden cols tid and tid+256
            float v0[16], v1[16];
            #pragma unroll
            for (int r = 0; r < 16; ++r) v0[r] = __ldcg(&g_hx[pr][row0 + r][tid]);
            #pragma unroll
            for (int r = 0; r < 16; ++r) v1[r] = __ldcg(&g_hx[pr][row0 + r][tid + 256]);
            float* d0 = &inpT[(9 + tid) * 20];
            float* d1 = &inpT[(9 + tid + 256) * 20];
            #pragma unroll
            for (int q = 0; q < 8; ++q) {
                *(float2*)(d0 + 2 * q) = make_float2(v0[2*q], v0[2*q+1]);
                *(float2*)(d1 + 2 * q) = make_float2(v1[2*q], v1[2*q+1]);
            }
        }
        __syncthreads();

        // ---- Phase C: software-pipelined mainloop. warp kp: k in [kp*68,+68),
        //      16 rows, cols (2*lane, 2*lane+1). Rotating prefetch: iter kk+1's
        //      loads issue during iter kk's FMAs.
        unsigned long long acc0[8], acc1[8];
        #pragma unroll
        for (int i = 0; i < 8; ++i) { acc0[i] = 0ull; acc1[i] = 0ull; }
        {
            const float* Ip = inpT + warp * 68 * 20;
            const float* Wp = Wsm + warp * 68 * 64 + 2 * lane;

            ulonglong2 ca = *(const ulonglong2*)(Ip + 0);
            ulonglong2 cb = *(const ulonglong2*)(Ip + 4);
            ulonglong2 cc = *(const ulonglong2*)(Ip + 8);
            ulonglong2 cd = *(const ulonglong2*)(Ip + 12);
            float2     cw = *(const float2*)(Wp);

            #pragma unroll 4
            for (int kk = 0; kk < 68; ++kk) {
                const int kn = (kk < 67) ? (kk + 1) : kk;   // last iter re-reads self
                const float* ipn = Ip + kn * 20;
                ulonglong2 na = *(const ulonglong2*)(ipn + 0);
                ulonglong2 nb = *(const ulonglong2*)(ipn + 4);
                ulonglong2 nc = *(const ulonglong2*)(ipn + 8);
                ulonglong2 nd = *(const ulonglong2*)(ipn + 12);
                float2     nw = *(const float2*)(Wp + kn * 64);

                unsigned long long w00, w11;
                asm("mov.b64 %0, {%1, %1};" : "=l"(w00) : "f"(cw.x));
                asm("mov.b64 %0, {%1, %1};" : "=l"(w11) : "f"(cw.y));
                unsigned long long pr_[8];
                pr_[0] = ca.x; pr_[1] = ca.y;
                pr_[2] = cb.x; pr_[3] = cb.y;
                pr_[4] = cc.x; pr_[5] = cc.y;
                pr_[6] = cd.x; pr_[7] = cd.y;
                #pragma unroll
                for (int p = 0; p < 8; ++p) {
                    asm("fma.rn.f32x2 %0, %1, %2, %0;" : "+l"(acc0[p]) : "l"(pr_[p]), "l"(w00));
                    asm("fma.rn.f32x2 %0, %1, %2, %0;" : "+l"(acc1[p]) : "l"(pr_[p]), "l"(w11));
                }
                ca = na; cb = nb; cc = nc; cd = nd; cw = nw;
            }
        }

        // ---- Phase D: spill k-partials, reduce, tanh, emit hx + readout partial ----
        #pragma unroll
        for (int p = 0; p < 8; ++p) {
            float2 a0 = *(float2*)&acc0[p];   // (row 2p, row 2p+1) col even
            float2 a1 = *(float2*)&acc1[p];   // col odd
            *(float2*)&red[(warp * 16 + 2 * p)     * 68 + 2 * lane] = make_float2(a0.x, a1.x);
            *(float2*)&red[(warp * 16 + 2 * p + 1) * 68 + 2 * lane] = make_float2(a0.y, a1.y);
        }
        __syncthreads();
        {
            int r = tid >> 4, c4 = (tid & 15) * 4;
            float4 v = make_float4(0.f, 0.f, 0.f, 0.f);
            #pragma unroll
            for (int w = 0; w < 8; ++w) {
                float4 p = *(const float4*)&red[(w * 16 + r) * 68 + c4];
                v.x += p.x; v.y += p.y; v.z += p.z; v.w += p.w;
            }
            v.x = tanhf(v.x + b1s[c4 + 0]);
            v.y = tanhf(v.y + b1s[c4 + 1]);
            v.z = tanhf(v.z + b1s[c4 + 2]);
            v.w = tanhf(v.w + b1s[c4 + 3]);
            *(float4*)&g_hx[pw][row0 + r][cg * 64 + c4] = v;
            float p = v.x * w2s[c4] + v.y * w2s[c4 + 1] + v.z * w2s[c4 + 2] + v.w * w2s[c4 + 3];
            #pragma unroll
            for (int off = 8; off > 0; off >>= 1)
                p += __shfl_xor_sync(0xffffffffu, p, off);
            if ((tid & 15) == 0) g_part[pw][rg][cg][r] = p;
        }

        // ---- Phase E: split cluster barrier; x staging hides in the gap ----
        asm volatile("barrier.cluster.arrive.aligned;" ::: "memory");
        if (t < 1023) {
            if (tid < 128) {
                inpT[xc * 20 + xr] = xpre;                           // stage x_{t+1}
                if (t < 1022) xpre = x[(row0 + xr) * 8192 + (t + 2) * 8 + xc];
            }
            // x0 for next step's Phase A = x_{t+1}[0]
            if (tid < 16) x0pre = x[(row0 + tid) * 8192 + (t + 1) * 8];
        }
        asm volatile("barrier.cluster.wait.aligned;" ::: "memory");
    }

    // epilogue: final output value out_{L-1}
    if (cg == 0 && tid < 16) {
        float o = b2v;
        #pragma unroll
        for (int g = 0; g < 8; ++g) o += __ldcg(&g_part[1][rg][g][tid]);
        outp[(row0 + tid) * 1024 + 1023] = o;
    }
}

extern "C" void kernel_launch(void* const* d_in, const int* in_sizes, int n_in,
                              void* d_out, int out_size) {
    const float* x  = (const float*)d_in[0];
    const float* W1 = (const float*)d_in[1];
    const float* b1 = (const float*)d_in[2];
    const float* W2 = (const float*)d_in[3];
    const float* b2 = (const float*)d_in[4];
    float* out = (float*)d_out;

    cudaFuncSetAttribute(resRNN_kernel, cudaFuncAttributeMaxDynamicSharedMemorySize, SMEM_BYTES);

    dim3 grid(8, 16, 1);   // cluster_dims (8,1,1): one cluster per rowgroup
    dim3 block(TPB, 1, 1);
    resRNN_kernel<<<grid, block, SMEM_BYTES>>>(x, W1, b1, W2, b2, out);
}